// round 2
// baseline (speedup 1.0000x reference)
#include <cuda_runtime.h>
#include <math.h>

// Problem constants
#define NN 50000
#define EE 800000
#define GG 64
constexpr int KDIM = 128;

// ---------------- device scratch (static; no allocation allowed) ----------------
__device__ int   g_cnt[NN];        // in-degree per node
__device__ int   g_rowptr[NN + 1]; // CSR row pointers (by dst)
__device__ int   g_cursor[NN];     // fill cursors
__device__ int   g_col[EE];        // src per CSR slot
__device__ float g_eattr[EE];      // edge_attr per CSR slot
__device__ float g_dis[NN];        // deg^{-1/2} (deg includes self loop)
__device__ int   g_gcnt[GG];       // nodes per graph
__device__ float g_y[NN * 128];    // y = dis * (x @ W)
__device__ float g_h[NN * 128];    // gcn output h
__device__ float g_act[NN * 128];  // layer activation

// ---------------- small vector helpers ----------------
template <int NV>
__device__ __forceinline__ void vload(float* d, const float* s) {
    if constexpr (NV == 4) {
        float4 v = *reinterpret_cast<const float4*>(s);
        d[0] = v.x; d[1] = v.y; d[2] = v.z; d[3] = v.w;
    } else {
        float2 v = *reinterpret_cast<const float2*>(s);
        d[0] = v.x; d[1] = v.y;
    }
}
template <int NV>
__device__ __forceinline__ void vstore(float* s, const float* d) {
    if constexpr (NV == 4) {
        *reinterpret_cast<float4*>(s) = make_float4(d[0], d[1], d[2], d[3]);
    } else {
        *reinterpret_cast<float2*>(s) = make_float2(d[0], d[1]);
    }
}

// ---------------- preprocessing kernels ----------------
__global__ void zero_kernel() {
    int i = blockIdx.x * blockDim.x + threadIdx.x;
    if (i < NN) g_cnt[i] = 0;
    if (i < GG) g_gcnt[i] = 0;
}

__global__ void count_kernel(const int* __restrict__ ei, const int* __restrict__ batch) {
    int i = blockIdx.x * blockDim.x + threadIdx.x;
    if (i < EE) atomicAdd(&g_cnt[ei[EE + i]], 1);
    if (i < NN) atomicAdd(&g_gcnt[batch[i]], 1);
}

// single-block exclusive scan of g_cnt -> g_rowptr / g_cursor
__global__ void scan_kernel() {
    __shared__ int wsum[32];
    __shared__ int s_carry, s_tot;
    int tid = threadIdx.x, lane = tid & 31, wid = tid >> 5;
    if (tid == 0) s_carry = 0;
    __syncthreads();
    for (int base = 0; base < NN; base += 1024) {
        int i = base + tid;
        int v = (i < NN) ? g_cnt[i] : 0;
        int val = v;
#pragma unroll
        for (int off = 1; off < 32; off <<= 1) {
            int t = __shfl_up_sync(0xffffffffu, val, off);
            if (lane >= off) val += t;
        }
        if (lane == 31) wsum[wid] = val;
        __syncthreads();
        if (wid == 0) {
            int wv = wsum[lane];
            int wi = wv;
#pragma unroll
            for (int off = 1; off < 32; off <<= 1) {
                int t = __shfl_up_sync(0xffffffffu, wi, off);
                if (lane >= off) wi += t;
            }
            wsum[lane] = wi - wv;  // exclusive warp offset
            if (lane == 31) s_tot = wi;
        }
        __syncthreads();
        int carry = s_carry;
        if (i < NN) {
            int excl = carry + wsum[wid] + (val - v);
            g_rowptr[i] = excl;
            g_cursor[i] = excl;
        }
        __syncthreads();
        if (tid == 0) s_carry = carry + s_tot;
        __syncthreads();
    }
    if (threadIdx.x == 0) g_rowptr[NN] = s_carry;
}

__global__ void dis_kernel() {
    int i = blockIdx.x * blockDim.x + threadIdx.x;
    if (i < NN) g_dis[i] = rsqrtf((float)g_cnt[i] + 1.0f);
}

__global__ void fill_kernel(const int* __restrict__ ei, const float* __restrict__ ea) {
    int i = blockIdx.x * blockDim.x + threadIdx.x;
    if (i < EE) {
        int d = ei[EE + i];
        int p = atomicAdd(&g_cursor[d], 1);
        g_col[p] = ei[i];
        g_eattr[p] = ea[i];
    }
}

// ---------------- GEMM: Y[row] = dis[row] * (X[row] @ W), X:[NN,128], W:[128,NOUT] ----------------
template <int NOUT, int BM>
__global__ void gemm_kernel(const float* __restrict__ X, const float* __restrict__ W,
                            float* __restrict__ Y) {
    constexpr int KK = 64;
    constexpr int CG = NOUT / 4;   // column groups (float4 per thread)
    constexpr int RG = 256 / CG;   // row groups
    static_assert(BM / RG == 4, "4 rows per thread");
    __shared__ __align__(16) float sW[KK * NOUT];
    __shared__ float sX[BM][KK + 1];

    int tid = threadIdx.x;
    int c = tid % CG;
    int rg = tid / CG;
    int row0 = blockIdx.x * BM;
    float acc[4][4] = {};

    for (int half = 0; half < 2; half++) {
        const float4* Wg4 = reinterpret_cast<const float4*>(W + half * KK * NOUT);
        float4* sW4 = reinterpret_cast<float4*>(sW);
        for (int idx = tid; idx < KK * NOUT / 4; idx += 256) sW4[idx] = Wg4[idx];
        for (int idx = tid; idx < BM * KK; idx += 256) {
            int r = idx / KK, k = idx % KK;
            int grow = row0 + r;
            sX[r][k] = (grow < NN) ? X[grow * KDIM + half * KK + k] : 0.f;
        }
        __syncthreads();
        const float4* sWv = reinterpret_cast<const float4*>(sW);
#pragma unroll
        for (int k = 0; k < KK; k++) {
            float4 w = sWv[k * CG + c];
#pragma unroll
            for (int i = 0; i < 4; i++) {
                float xv = sX[rg * 4 + i][k];
                acc[i][0] += xv * w.x;
                acc[i][1] += xv * w.y;
                acc[i][2] += xv * w.z;
                acc[i][3] += xv * w.w;
            }
        }
        __syncthreads();
    }
#pragma unroll
    for (int i = 0; i < 4; i++) {
        int row = row0 + rg * 4 + i;
        if (row < NN) {
            float d = g_dis[row];
            float4 o = make_float4(acc[i][0] * d, acc[i][1] * d, acc[i][2] * d, acc[i][3] * d);
            *reinterpret_cast<float4*>(&Y[(size_t)row * NOUT + c * 4]) = o;
        }
    }
}

// ---------------- gather 1: h[v] = dis[v]*(sum_{u in in(v)} y[u] + y[v]) + b ----------------
template <int NOUT>
__global__ void gather1_kernel(const float* __restrict__ y, const float* __restrict__ bias,
                               float* __restrict__ h) {
    constexpr int NV = NOUT / 32;
    int warp = (blockIdx.x * blockDim.x + threadIdx.x) >> 5;
    if (warp >= NN) return;
    int lane = threadIdx.x & 31;
    int beg = g_rowptr[warp], end = g_rowptr[warp + 1];
    float acc[NV];
    vload<NV>(acc, y + (size_t)warp * NOUT + lane * NV);  // self term
    int e = beg;
    for (; e + 4 <= end; e += 4) {
        int u0 = g_col[e], u1 = g_col[e + 1], u2 = g_col[e + 2], u3 = g_col[e + 3];
        float t0[NV], t1[NV], t2[NV], t3[NV];
        vload<NV>(t0, y + (size_t)u0 * NOUT + lane * NV);
        vload<NV>(t1, y + (size_t)u1 * NOUT + lane * NV);
        vload<NV>(t2, y + (size_t)u2 * NOUT + lane * NV);
        vload<NV>(t3, y + (size_t)u3 * NOUT + lane * NV);
#pragma unroll
        for (int j = 0; j < NV; j++) acc[j] += (t0[j] + t1[j]) + (t2[j] + t3[j]);
    }
    for (; e < end; e++) {
        int u = g_col[e];
        float t[NV];
        vload<NV>(t, y + (size_t)u * NOUT + lane * NV);
#pragma unroll
        for (int j = 0; j < NV; j++) acc[j] += t[j];
    }
    float d = g_dis[warp];
    float b[NV];
    vload<NV>(b, bias + lane * NV);
    float o[NV];
#pragma unroll
    for (int j = 0; j < NV; j++) o[j] = acc[j] * d + b[j];
    vstore<NV>(h + (size_t)warp * NOUT + lane * NV, o);
}

// ---------------- gather 2 + relu + LayerNorm (hidden layers, NOUT=128) ----------------
__global__ void gather2_ln_kernel(const float* __restrict__ h, const float* __restrict__ ew,
                                  const float* __restrict__ eb, const float* __restrict__ lg,
                                  const float* __restrict__ lb, float* __restrict__ act) {
    int warp = (blockIdx.x * blockDim.x + threadIdx.x) >> 5;
    if (warp >= NN) return;
    int lane = threadIdx.x & 31;
    float4 ew4 = *reinterpret_cast<const float4*>(ew + lane * 4);
    float4 eb4 = *reinterpret_cast<const float4*>(eb + lane * 4);
    int beg = g_rowptr[warp], end = g_rowptr[warp + 1];
    float a0 = 0.f, a1 = 0.f, a2 = 0.f, a3 = 0.f;
    int e = beg;
    for (; e + 4 <= end; e += 4) {
        int u0 = g_col[e], u1 = g_col[e + 1], u2 = g_col[e + 2], u3 = g_col[e + 3];
        float at0 = g_eattr[e], at1 = g_eattr[e + 1], at2 = g_eattr[e + 2], at3 = g_eattr[e + 3];
        float4 t0 = *reinterpret_cast<const float4*>(h + (size_t)u0 * 128 + lane * 4);
        float4 t1 = *reinterpret_cast<const float4*>(h + (size_t)u1 * 128 + lane * 4);
        float4 t2 = *reinterpret_cast<const float4*>(h + (size_t)u2 * 128 + lane * 4);
        float4 t3 = *reinterpret_cast<const float4*>(h + (size_t)u3 * 128 + lane * 4);
        a0 += t0.x + fmaxf(at0 * ew4.x + eb4.x, 0.f) + t1.x + fmaxf(at1 * ew4.x + eb4.x, 0.f)
            + t2.x + fmaxf(at2 * ew4.x + eb4.x, 0.f) + t3.x + fmaxf(at3 * ew4.x + eb4.x, 0.f);
        a1 += t0.y + fmaxf(at0 * ew4.y + eb4.y, 0.f) + t1.y + fmaxf(at1 * ew4.y + eb4.y, 0.f)
            + t2.y + fmaxf(at2 * ew4.y + eb4.y, 0.f) + t3.y + fmaxf(at3 * ew4.y + eb4.y, 0.f);
        a2 += t0.z + fmaxf(at0 * ew4.z + eb4.z, 0.f) + t1.z + fmaxf(at1 * ew4.z + eb4.z, 0.f)
            + t2.z + fmaxf(at2 * ew4.z + eb4.z, 0.f) + t3.z + fmaxf(at3 * ew4.z + eb4.z, 0.f);
        a3 += t0.w + fmaxf(at0 * ew4.w + eb4.w, 0.f) + t1.w + fmaxf(at1 * ew4.w + eb4.w, 0.f)
            + t2.w + fmaxf(at2 * ew4.w + eb4.w, 0.f) + t3.w + fmaxf(at3 * ew4.w + eb4.w, 0.f);
    }
    for (; e < end; e++) {
        int u = g_col[e];
        float at = g_eattr[e];
        float4 t = *reinterpret_cast<const float4*>(h + (size_t)u * 128 + lane * 4);
        a0 += t.x + fmaxf(at * ew4.x + eb4.x, 0.f);
        a1 += t.y + fmaxf(at * ew4.y + eb4.y, 0.f);
        a2 += t.z + fmaxf(at * ew4.z + eb4.z, 0.f);
        a3 += t.w + fmaxf(at * ew4.w + eb4.w, 0.f);
    }
    float inv = 1.f / fmaxf((float)(end - beg), 1.f);
    a0 = fmaxf(a0 * inv, 0.f);
    a1 = fmaxf(a1 * inv, 0.f);
    a2 = fmaxf(a2 * inv, 0.f);
    a3 = fmaxf(a3 * inv, 0.f);
    float s = a0 + a1 + a2 + a3;
    float q = a0 * a0 + a1 * a1 + a2 * a2 + a3 * a3;
#pragma unroll
    for (int off = 16; off; off >>= 1) {
        s += __shfl_xor_sync(0xffffffffu, s, off);
        q += __shfl_xor_sync(0xffffffffu, q, off);
    }
    float mu = s * (1.f / 128.f);
    float var = q * (1.f / 128.f) - mu * mu;
    float rstd = rsqrtf(var + 1e-5f);
    float4 g4 = *reinterpret_cast<const float4*>(lg + lane * 4);
    float4 b4 = *reinterpret_cast<const float4*>(lb + lane * 4);
    float4 o = make_float4((a0 - mu) * rstd * g4.x + b4.x, (a1 - mu) * rstd * g4.y + b4.y,
                           (a2 - mu) * rstd * g4.z + b4.z, (a3 - mu) * rstd * g4.w + b4.w);
    *reinterpret_cast<float4*>(act + (size_t)warp * 128 + lane * 4) = o;
}

// ---------------- gather 2 final layer (NOUT=64, no relu/LN), writes d_out ----------------
__global__ void gather2_final_kernel(const float* __restrict__ h, const float* __restrict__ ew,
                                     const float* __restrict__ eb, float* __restrict__ out) {
    int warp = (blockIdx.x * blockDim.x + threadIdx.x) >> 5;
    if (warp >= NN) return;
    int lane = threadIdx.x & 31;
    float2 ew2 = *reinterpret_cast<const float2*>(ew + lane * 2);
    float2 eb2 = *reinterpret_cast<const float2*>(eb + lane * 2);
    int beg = g_rowptr[warp], end = g_rowptr[warp + 1];
    float a0 = 0.f, a1 = 0.f;
    int e = beg;
    for (; e + 4 <= end; e += 4) {
        int u0 = g_col[e], u1 = g_col[e + 1], u2 = g_col[e + 2], u3 = g_col[e + 3];
        float at0 = g_eattr[e], at1 = g_eattr[e + 1], at2 = g_eattr[e + 2], at3 = g_eattr[e + 3];
        float2 t0 = *reinterpret_cast<const float2*>(h + (size_t)u0 * 64 + lane * 2);
        float2 t1 = *reinterpret_cast<const float2*>(h + (size_t)u1 * 64 + lane * 2);
        float2 t2 = *reinterpret_cast<const float2*>(h + (size_t)u2 * 64 + lane * 2);
        float2 t3 = *reinterpret_cast<const float2*>(h + (size_t)u3 * 64 + lane * 2);
        a0 += t0.x + fmaxf(at0 * ew2.x + eb2.x, 0.f) + t1.x + fmaxf(at1 * ew2.x + eb2.x, 0.f)
            + t2.x + fmaxf(at2 * ew2.x + eb2.x, 0.f) + t3.x + fmaxf(at3 * ew2.x + eb2.x, 0.f);
        a1 += t0.y + fmaxf(at0 * ew2.y + eb2.y, 0.f) + t1.y + fmaxf(at1 * ew2.y + eb2.y, 0.f)
            + t2.y + fmaxf(at2 * ew2.y + eb2.y, 0.f) + t3.y + fmaxf(at3 * ew2.y + eb2.y, 0.f);
    }
    for (; e < end; e++) {
        int u = g_col[e];
        float at = g_eattr[e];
        float2 t = *reinterpret_cast<const float2*>(h + (size_t)u * 64 + lane * 2);
        a0 += t.x + fmaxf(at * ew2.x + eb2.x, 0.f);
        a1 += t.y + fmaxf(at * ew2.y + eb2.y, 0.f);
    }
    float inv = 1.f / fmaxf((float)(end - beg), 1.f);
    *reinterpret_cast<float2*>(out + (size_t)warp * 64 + lane * 2) =
        make_float2(a0 * inv, a1 * inv);
}

// ---------------- global mean pool: block per graph (batch is sorted) ----------------
__global__ void pool_kernel(float* __restrict__ out) {
    __shared__ float sred[256];
    __shared__ int s_start, s_cnt;
    int g = blockIdx.x, t = threadIdx.x;
    if (t == 0) {
        int st = 0;
        for (int j = 0; j < g; j++) st += g_gcnt[j];
        s_start = st;
        s_cnt = g_gcnt[g];
    }
    __syncthreads();
    int start = s_start, cnt = s_cnt;
    int f = t & 63, sub = t >> 6;
    float p = 0.f;
    for (int i = start + sub; i < start + cnt; i += 4) p += out[(size_t)i * 64 + f];
    sred[t] = p;
    __syncthreads();
    if (t < 64) {
        float s = sred[t] + sred[t + 64] + sred[t + 128] + sred[t + 192];
        out[(size_t)NN * 64 + g * 64 + f] = s / fmaxf((float)cnt, 1.0f);
    }
}

// ---------------- launch ----------------
extern "C" void kernel_launch(void* const* d_in, const int* in_sizes, int n_in,
                              void* d_out, int out_size) {
    const float* x = (const float*)d_in[0];
    const int* ei = (const int*)d_in[1];
    const float* ea = (const float*)d_in[2];
    const int* batch = (const int*)d_in[3];
    const float* gw0 = (const float*)d_in[4];
    const float* gb0 = (const float*)d_in[5];
    const float* ew0 = (const float*)d_in[6];
    const float* eb0 = (const float*)d_in[7];
    const float* lg0 = (const float*)d_in[8];
    const float* lb0 = (const float*)d_in[9];
    const float* gw1 = (const float*)d_in[10];
    const float* gb1 = (const float*)d_in[11];
    const float* ew1 = (const float*)d_in[12];
    const float* eb1 = (const float*)d_in[13];
    const float* lg1 = (const float*)d_in[14];
    const float* lb1 = (const float*)d_in[15];
    const float* gw2 = (const float*)d_in[16];
    const float* gb2 = (const float*)d_in[17];
    const float* ew2 = (const float*)d_in[18];
    const float* eb2 = (const float*)d_in[19];
    float* out = (float*)d_out;

    float *yp, *hp, *ap;
    cudaGetSymbolAddress((void**)&yp, g_y);
    cudaGetSymbolAddress((void**)&hp, g_h);
    cudaGetSymbolAddress((void**)&ap, g_act);

    const int WARP_GRID = (NN * 32 + 255) / 256;

    zero_kernel<<<(NN + 255) / 256, 256>>>();
    count_kernel<<<(EE + 255) / 256, 256>>>(ei, batch);
    scan_kernel<<<1, 1024>>>();
    dis_kernel<<<(NN + 255) / 256, 256>>>();
    fill_kernel<<<(EE + 255) / 256, 256>>>(ei, ea);

    // layer 0: 128 -> 128
    gemm_kernel<128, 32><<<(NN + 31) / 32, 256>>>(x, gw0, yp);
    gather1_kernel<128><<<WARP_GRID, 256>>>(yp, gb0, hp);
    gather2_ln_kernel<<<WARP_GRID, 256>>>(hp, ew0, eb0, lg0, lb0, ap);

    // layer 1: 128 -> 128
    gemm_kernel<128, 32><<<(NN + 31) / 32, 256>>>(ap, gw1, yp);
    gather1_kernel<128><<<WARP_GRID, 256>>>(yp, gb1, hp);
    gather2_ln_kernel<<<WARP_GRID, 256>>>(hp, ew1, eb1, lg1, lb1, ap);

    // layer 2: 128 -> 64
    gemm_kernel<64, 64><<<(NN + 63) / 64, 256>>>(ap, gw2, yp);
    gather1_kernel<64><<<WARP_GRID, 256>>>(yp, gb2, hp);
    gather2_final_kernel<<<WARP_GRID, 256>>>(hp, ew2, eb2, out);

    // global mean pool into out[NN*64 ..]
    pool_kernel<<<GG, 256>>>(out);
}

// round 3
// speedup vs baseline: 1.2665x; 1.2665x over previous
#include <cuda_runtime.h>
#include <cuda_fp16.h>
#include <mma.h>
#include <math.h>
using namespace nvcuda;

// Problem constants
#define NN 50000
#define PADN 50048   // padded to multiple of 128 for GEMM tiles
#define EE 800000
#define GG 64

// ---------------- device scratch (static; no allocation allowed) ----------------
__device__ int    g_cnt[NN];
__device__ int    g_rowptr[NN + 1];
__device__ int    g_cursor[NN];
__device__ int    g_col[EE];
__device__ float  g_eattr[EE];
__device__ float  g_dis[NN];
__device__ int    g_gcnt[GG];
__device__ __half g_xh[PADN * 128];   // dis-scaled fp16 layer input
__device__ __half g_w0h[128 * 128];
__device__ __half g_w1h[128 * 128];
__device__ __half g_w2h[128 * 64];
__device__ __half g_y[PADN * 128];    // GEMM out: dis ⊙ (in @ W)
__device__ __half g_h[PADN * 128];    // gcn out
__device__ __half g_act[PADN * 128];  // dis-scaled activation (next GEMM input)

// ---------------- preprocessing ----------------
__global__ void zero_kernel() {
    int i = blockIdx.x * blockDim.x + threadIdx.x;
    if (i < NN) g_cnt[i] = 0;
    if (i < GG) g_gcnt[i] = 0;
}

__global__ void count_kernel(const int* __restrict__ ei, const int* __restrict__ batch) {
    int i = blockIdx.x * blockDim.x + threadIdx.x;
    if (i < EE) atomicAdd(&g_cnt[ei[EE + i]], 1);
    if (i < NN) atomicAdd(&g_gcnt[batch[i]], 1);
}

__global__ void scan_kernel() {
    __shared__ int wsum[32];
    __shared__ int s_carry, s_tot;
    int tid = threadIdx.x, lane = tid & 31, wid = tid >> 5;
    if (tid == 0) s_carry = 0;
    __syncthreads();
    for (int base = 0; base < NN; base += 1024) {
        int i = base + tid;
        int v = (i < NN) ? g_cnt[i] : 0;
        int val = v;
#pragma unroll
        for (int off = 1; off < 32; off <<= 1) {
            int t = __shfl_up_sync(0xffffffffu, val, off);
            if (lane >= off) val += t;
        }
        if (lane == 31) wsum[wid] = val;
        __syncthreads();
        if (wid == 0) {
            int wv = wsum[lane];
            int wi = wv;
#pragma unroll
            for (int off = 1; off < 32; off <<= 1) {
                int t = __shfl_up_sync(0xffffffffu, wi, off);
                if (lane >= off) wi += t;
            }
            wsum[lane] = wi - wv;
            if (lane == 31) s_tot = wi;
        }
        __syncthreads();
        int carry = s_carry;
        if (i < NN) {
            int excl = carry + wsum[wid] + (val - v);
            g_rowptr[i] = excl;
            g_cursor[i] = excl;
        }
        __syncthreads();
        if (tid == 0) s_carry = carry + s_tot;
        __syncthreads();
    }
    if (threadIdx.x == 0) g_rowptr[NN] = s_carry;
}

__global__ void dis_kernel() {
    int i = blockIdx.x * blockDim.x + threadIdx.x;
    if (i < NN) g_dis[i] = rsqrtf((float)g_cnt[i] + 1.0f);
}

__global__ void fill_kernel(const int* __restrict__ ei, const float* __restrict__ ea) {
    int i = blockIdx.x * blockDim.x + threadIdx.x;
    if (i < EE) {
        int d = ei[EE + i];
        int p = atomicAdd(&g_cursor[d], 1);
        g_col[p] = ei[i];
        g_eattr[p] = ea[i];
    }
}

// ---------------- conversions ----------------
// x (fp32) -> g_xh (fp16), scaled by dis[row]; pad rows zero
__global__ void convert_x_kernel(const float* __restrict__ x) {
    int i = blockIdx.x * blockDim.x + threadIdx.x;  // 4 floats each
    int base = i * 4;
    if (base >= PADN * 128) return;
    int row = base >> 7;
    uint2 o;
    if (row < NN) {
        float4 v = *reinterpret_cast<const float4*>(x + base);
        float d = g_dis[row];
        __half2 h0 = __floats2half2_rn(v.x * d, v.y * d);
        __half2 h1 = __floats2half2_rn(v.z * d, v.w * d);
        o.x = *reinterpret_cast<unsigned*>(&h0);
        o.y = *reinterpret_cast<unsigned*>(&h1);
    } else {
        o.x = 0u; o.y = 0u;
    }
    *reinterpret_cast<uint2*>(g_xh + base) = o;
}

__global__ void convert_w_kernel(const float* __restrict__ w0, const float* __restrict__ w1,
                                 const float* __restrict__ w2) {
    int i = blockIdx.x * blockDim.x + threadIdx.x;  // half2 units
    const float* src;
    __half* dst;
    int off;
    if (i < 8192) { src = w0; dst = g_w0h; off = i; }
    else if (i < 16384) { src = w1; dst = g_w1h; off = i - 8192; }
    else if (i < 20480) { src = w2; dst = g_w2h; off = i - 16384; }
    else return;
    float2 v = *reinterpret_cast<const float2*>(src + off * 2);
    *reinterpret_cast<__half2*>(dst + off * 2) = __floats2half2_rn(v.x, v.y);
}

// ---------------- HMMA GEMM: Y = A @ W (A rows already dis-scaled) ----------------
// A: [PADN,128] fp16 row-major, W: [128,NOUT] fp16 row-major, Y: [PADN,NOUT] fp16
template <int NOUT, int BM>
__global__ void hgemm_kernel(const __half* __restrict__ A, const __half* __restrict__ Bw,
                             __half* __restrict__ Y) {
    constexpr int KC = 64;
    constexpr int WARPS_M = BM / 16;
    constexpr int LDA = KC + 8;
    constexpr int LDB = NOUT + 8;
    constexpr int A_BYTES = BM * LDA * 2;
    constexpr int B_BYTES = KC * LDB * 2;
    constexpr int SMEM_BYTES = (A_BYTES + B_BYTES) > 32768 ? (A_BYTES + B_BYTES) : 32768;
    __shared__ __align__(16) char smem_raw[SMEM_BYTES];
    __half* sA = reinterpret_cast<__half*>(smem_raw);
    __half* sB = reinterpret_cast<__half*>(smem_raw + A_BYTES);

    int tid = threadIdx.x;
    int warp = tid >> 5, lane = tid & 31;
    int wm = warp % WARPS_M, wn = warp / WARPS_M;
    int row0 = blockIdx.x * BM;

    wmma::fragment<wmma::accumulator, 16, 16, 16, float> acc[4];
#pragma unroll
    for (int f = 0; f < 4; f++) wmma::fill_fragment(acc[f], 0.f);

    for (int kc = 0; kc < 2; kc++) {
        for (int idx = tid; idx < BM * KC / 8; idx += 256) {
            int r = idx / (KC / 8), cg = idx % (KC / 8);
            *reinterpret_cast<int4*>(sA + r * LDA + cg * 8) =
                *reinterpret_cast<const int4*>(A + (size_t)(row0 + r) * 128 + kc * KC + cg * 8);
        }
        for (int idx = tid; idx < KC * NOUT / 8; idx += 256) {
            int r = idx / (NOUT / 8), cg = idx % (NOUT / 8);
            *reinterpret_cast<int4*>(sB + r * LDB + cg * 8) =
                *reinterpret_cast<const int4*>(Bw + (size_t)(kc * KC + r) * NOUT + cg * 8);
        }
        __syncthreads();
#pragma unroll
        for (int k16 = 0; k16 < 4; k16++) {
            wmma::fragment<wmma::matrix_a, 16, 16, 16, __half, wmma::row_major> af;
            wmma::load_matrix_sync(af, sA + (wm * 16) * LDA + k16 * 16, LDA);
#pragma unroll
            for (int f = 0; f < 4; f++) {
                wmma::fragment<wmma::matrix_b, 16, 16, 16, __half, wmma::row_major> bf;
                wmma::load_matrix_sync(bf, sB + (k16 * 16) * LDB + wn * 64 + f * 16, LDB);
                wmma::mma_sync(acc[f], af, bf, acc[f]);
            }
        }
        __syncthreads();
    }
    // epilogue: stage fp32 through smem (per-warp region), convert to fp16
    float* stage = reinterpret_cast<float*>(smem_raw) + warp * 16 * 64;
#pragma unroll
    for (int f = 0; f < 4; f++)
        wmma::store_matrix_sync(stage + f * 16, acc[f], 64, wmma::mem_row_major);
    __syncwarp();
    for (int idx = lane; idx < 256; idx += 32) {
        int r = idx >> 4, c4 = (idx & 15) * 4;
        float4 v = *reinterpret_cast<float4*>(stage + r * 64 + c4);
        __half2 h0 = __floats2half2_rn(v.x, v.y);
        __half2 h1 = __floats2half2_rn(v.z, v.w);
        uint2 o;
        o.x = *reinterpret_cast<unsigned*>(&h0);
        o.y = *reinterpret_cast<unsigned*>(&h1);
        *reinterpret_cast<uint2*>(Y + (size_t)(row0 + wm * 16 + r) * NOUT + wn * 64 + c4) = o;
    }
}

// ---------------- fp16 row helpers ----------------
template <int NH>
__device__ __forceinline__ void row_load(float* t, const __half* p) {
    if constexpr (NH == 4) {
        uint2 v = *reinterpret_cast<const uint2*>(p);
        __half2 h0 = *reinterpret_cast<__half2*>(&v.x);
        __half2 h1 = *reinterpret_cast<__half2*>(&v.y);
        float2 f0 = __half22float2(h0), f1 = __half22float2(h1);
        t[0] = f0.x; t[1] = f0.y; t[2] = f1.x; t[3] = f1.y;
    } else {
        __half2 h = *reinterpret_cast<const __half2*>(p);
        float2 f = __half22float2(h);
        t[0] = f.x; t[1] = f.y;
    }
}

// ---------------- gather 1: h[v] = dis[v]*(sum_in y[u] + y[v]) + b ----------------
template <int NOUT>
__global__ void gather1_kernel(const __half* __restrict__ y, const float* __restrict__ bias,
                               __half* __restrict__ h) {
    constexpr int NH = NOUT / 32;
    int warp = (blockIdx.x * blockDim.x + threadIdx.x) >> 5;
    if (warp >= NN) return;
    int lane = threadIdx.x & 31;
    int beg = g_rowptr[warp], end = g_rowptr[warp + 1];
    float acc[NH] = {};
    row_load<NH>(acc, y + (size_t)warp * NOUT + lane * NH);  // self term
    int e = beg;
    for (; e + 4 <= end; e += 4) {
        int u0 = g_col[e], u1 = g_col[e + 1], u2 = g_col[e + 2], u3 = g_col[e + 3];
        float t0[NH], t1[NH], t2[NH], t3[NH];
        row_load<NH>(t0, y + (size_t)u0 * NOUT + lane * NH);
        row_load<NH>(t1, y + (size_t)u1 * NOUT + lane * NH);
        row_load<NH>(t2, y + (size_t)u2 * NOUT + lane * NH);
        row_load<NH>(t3, y + (size_t)u3 * NOUT + lane * NH);
#pragma unroll
        for (int j = 0; j < NH; j++) acc[j] += (t0[j] + t1[j]) + (t2[j] + t3[j]);
    }
    for (; e < end; e++) {
        int u = g_col[e];
        float t[NH];
        row_load<NH>(t, y + (size_t)u * NOUT + lane * NH);
#pragma unroll
        for (int j = 0; j < NH; j++) acc[j] += t[j];
    }
    float d = g_dis[warp];
    if constexpr (NH == 4) {
        float4 b = *reinterpret_cast<const float4*>(bias + lane * 4);
        __half2 h0 = __floats2half2_rn(acc[0] * d + b.x, acc[1] * d + b.y);
        __half2 h1 = __floats2half2_rn(acc[2] * d + b.z, acc[3] * d + b.w);
        uint2 o;
        o.x = *reinterpret_cast<unsigned*>(&h0);
        o.y = *reinterpret_cast<unsigned*>(&h1);
        *reinterpret_cast<uint2*>(h + (size_t)warp * NOUT + lane * 4) = o;
    } else {
        float2 b = *reinterpret_cast<const float2*>(bias + lane * 2);
        *reinterpret_cast<__half2*>(h + (size_t)warp * 64 + lane * 2) =
            __floats2half2_rn(acc[0] * d + b.x, acc[1] * d + b.y);
    }
}

// ---------------- gather 2 + relu + LN, output dis-scaled fp16 (hidden layers) ----------------
__global__ void gather2_ln_kernel(const __half* __restrict__ h, const float* __restrict__ ew,
                                  const float* __restrict__ eb, const float* __restrict__ lg,
                                  const float* __restrict__ lb, __half* __restrict__ act) {
    int warp = (blockIdx.x * blockDim.x + threadIdx.x) >> 5;
    if (warp >= NN) return;
    int lane = threadIdx.x & 31;
    float4 ew4 = *reinterpret_cast<const float4*>(ew + lane * 4);
    float4 eb4 = *reinterpret_cast<const float4*>(eb + lane * 4);
    int beg = g_rowptr[warp], end = g_rowptr[warp + 1];
    float a0 = 0.f, a1 = 0.f, a2 = 0.f, a3 = 0.f;
    int e = beg;
    for (; e + 4 <= end; e += 4) {
        int u0 = g_col[e], u1 = g_col[e + 1], u2 = g_col[e + 2], u3 = g_col[e + 3];
        float at0 = g_eattr[e], at1 = g_eattr[e + 1], at2 = g_eattr[e + 2], at3 = g_eattr[e + 3];
        float t0[4], t1[4], t2[4], t3[4];
        row_load<4>(t0, h + (size_t)u0 * 128 + lane * 4);
        row_load<4>(t1, h + (size_t)u1 * 128 + lane * 4);
        row_load<4>(t2, h + (size_t)u2 * 128 + lane * 4);
        row_load<4>(t3, h + (size_t)u3 * 128 + lane * 4);
        a0 += t0[0] + fmaxf(at0 * ew4.x + eb4.x, 0.f) + t1[0] + fmaxf(at1 * ew4.x + eb4.x, 0.f)
            + t2[0] + fmaxf(at2 * ew4.x + eb4.x, 0.f) + t3[0] + fmaxf(at3 * ew4.x + eb4.x, 0.f);
        a1 += t0[1] + fmaxf(at0 * ew4.y + eb4.y, 0.f) + t1[1] + fmaxf(at1 * ew4.y + eb4.y, 0.f)
            + t2[1] + fmaxf(at2 * ew4.y + eb4.y, 0.f) + t3[1] + fmaxf(at3 * ew4.y + eb4.y, 0.f);
        a2 += t0[2] + fmaxf(at0 * ew4.z + eb4.z, 0.f) + t1[2] + fmaxf(at1 * ew4.z + eb4.z, 0.f)
            + t2[2] + fmaxf(at2 * ew4.z + eb4.z, 0.f) + t3[2] + fmaxf(at3 * ew4.z + eb4.z, 0.f);
        a3 += t0[3] + fmaxf(at0 * ew4.w + eb4.w, 0.f) + t1[3] + fmaxf(at1 * ew4.w + eb4.w, 0.f)
            + t2[3] + fmaxf(at2 * ew4.w + eb4.w, 0.f) + t3[3] + fmaxf(at3 * ew4.w + eb4.w, 0.f);
    }
    for (; e < end; e++) {
        int u = g_col[e];
        float at = g_eattr[e];
        float t[4];
        row_load<4>(t, h + (size_t)u * 128 + lane * 4);
        a0 += t[0] + fmaxf(at * ew4.x + eb4.x, 0.f);
        a1 += t[1] + fmaxf(at * ew4.y + eb4.y, 0.f);
        a2 += t[2] + fmaxf(at * ew4.z + eb4.z, 0.f);
        a3 += t[3] + fmaxf(at * ew4.w + eb4.w, 0.f);
    }
    float inv = 1.f / fmaxf((float)(end - beg), 1.f);
    a0 = fmaxf(a0 * inv, 0.f);
    a1 = fmaxf(a1 * inv, 0.f);
    a2 = fmaxf(a2 * inv, 0.f);
    a3 = fmaxf(a3 * inv, 0.f);
    float s = a0 + a1 + a2 + a3;
    float q = a0 * a0 + a1 * a1 + a2 * a2 + a3 * a3;
#pragma unroll
    for (int off = 16; off; off >>= 1) {
        s += __shfl_xor_sync(0xffffffffu, s, off);
        q += __shfl_xor_sync(0xffffffffu, q, off);
    }
    float mu = s * (1.f / 128.f);
    float var = q * (1.f / 128.f) - mu * mu;
    float rstd = rsqrtf(var + 1e-5f);
    float4 g4 = *reinterpret_cast<const float4*>(lg + lane * 4);
    float4 b4 = *reinterpret_cast<const float4*>(lb + lane * 4);
    float d = g_dis[warp];  // pre-scale next-layer GEMM input
    __half2 h0 = __floats2half2_rn(((a0 - mu) * rstd * g4.x + b4.x) * d,
                                   ((a1 - mu) * rstd * g4.y + b4.y) * d);
    __half2 h1 = __floats2half2_rn(((a2 - mu) * rstd * g4.z + b4.z) * d,
                                   ((a3 - mu) * rstd * g4.w + b4.w) * d);
    uint2 o;
    o.x = *reinterpret_cast<unsigned*>(&h0);
    o.y = *reinterpret_cast<unsigned*>(&h1);
    *reinterpret_cast<uint2*>(act + (size_t)warp * 128 + lane * 4) = o;
}

// ---------------- gather 2 final layer (NOUT=64), writes fp32 d_out ----------------
__global__ void gather2_final_kernel(const __half* __restrict__ h, const float* __restrict__ ew,
                                     const float* __restrict__ eb, float* __restrict__ out) {
    int warp = (blockIdx.x * blockDim.x + threadIdx.x) >> 5;
    if (warp >= NN) return;
    int lane = threadIdx.x & 31;
    float2 ew2 = *reinterpret_cast<const float2*>(ew + lane * 2);
    float2 eb2 = *reinterpret_cast<const float2*>(eb + lane * 2);
    int beg = g_rowptr[warp], end = g_rowptr[warp + 1];
    float a0 = 0.f, a1 = 0.f;
    int e = beg;
    for (; e + 4 <= end; e += 4) {
        int u0 = g_col[e], u1 = g_col[e + 1], u2 = g_col[e + 2], u3 = g_col[e + 3];
        float at0 = g_eattr[e], at1 = g_eattr[e + 1], at2 = g_eattr[e + 2], at3 = g_eattr[e + 3];
        float t0[2], t1[2], t2[2], t3[2];
        row_load<2>(t0, h + (size_t)u0 * 64 + lane * 2);
        row_load<2>(t1, h + (size_t)u1 * 64 + lane * 2);
        row_load<2>(t2, h + (size_t)u2 * 64 + lane * 2);
        row_load<2>(t3, h + (size_t)u3 * 64 + lane * 2);
        a0 += t0[0] + fmaxf(at0 * ew2.x + eb2.x, 0.f) + t1[0] + fmaxf(at1 * ew2.x + eb2.x, 0.f)
            + t2[0] + fmaxf(at2 * ew2.x + eb2.x, 0.f) + t3[0] + fmaxf(at3 * ew2.x + eb2.x, 0.f);
        a1 += t0[1] + fmaxf(at0 * ew2.y + eb2.y, 0.f) + t1[1] + fmaxf(at1 * ew2.y + eb2.y, 0.f)
            + t2[1] + fmaxf(at2 * ew2.y + eb2.y, 0.f) + t3[1] + fmaxf(at3 * ew2.y + eb2.y, 0.f);
    }
    for (; e < end; e++) {
        int u = g_col[e];
        float at = g_eattr[e];
        float t[2];
        row_load<2>(t, h + (size_t)u * 64 + lane * 2);
        a0 += t[0] + fmaxf(at * ew2.x + eb2.x, 0.f);
        a1 += t[1] + fmaxf(at * ew2.y + eb2.y, 0.f);
    }
    float inv = 1.f / fmaxf((float)(end - beg), 1.f);
    *reinterpret_cast<float2*>(out + (size_t)warp * 64 + lane * 2) =
        make_float2(a0 * inv, a1 * inv);
}

// ---------------- global mean pool ----------------
__global__ void pool_kernel(float* __restrict__ out) {
    __shared__ float sred[256];
    __shared__ int s_start, s_cnt;
    int g = blockIdx.x, t = threadIdx.x;
    if (t == 0) {
        int st = 0;
        for (int j = 0; j < g; j++) st += g_gcnt[j];
        s_start = st;
        s_cnt = g_gcnt[g];
    }
    __syncthreads();
    int start = s_start, cnt = s_cnt;
    int f = t & 63, sub = t >> 6;
    float p = 0.f;
    for (int i = start + sub; i < start + cnt; i += 4) p += out[(size_t)i * 64 + f];
    sred[t] = p;
    __syncthreads();
    if (t < 64) {
        float s = sred[t] + sred[t + 64] + sred[t + 128] + sred[t + 192];
        out[(size_t)NN * 64 + g * 64 + f] = s / fmaxf((float)cnt, 1.0f);
    }
}

// ---------------- launch ----------------
extern "C" void kernel_launch(void* const* d_in, const int* in_sizes, int n_in,
                              void* d_out, int out_size) {
    const float* x = (const float*)d_in[0];
    const int* ei = (const int*)d_in[1];
    const float* ea = (const float*)d_in[2];
    const int* batch = (const int*)d_in[3];
    const float* gw0 = (const float*)d_in[4];
    const float* gb0 = (const float*)d_in[5];
    const float* ew0 = (const float*)d_in[6];
    const float* eb0 = (const float*)d_in[7];
    const float* lg0 = (const float*)d_in[8];
    const float* lb0 = (const float*)d_in[9];
    const float* gw1 = (const float*)d_in[10];
    const float* gb1 = (const float*)d_in[11];
    const float* ew1 = (const float*)d_in[12];
    const float* eb1 = (const float*)d_in[13];
    const float* lg1 = (const float*)d_in[14];
    const float* lb1 = (const float*)d_in[15];
    const float* gw2 = (const float*)d_in[16];
    const float* gb2 = (const float*)d_in[17];
    const float* ew2 = (const float*)d_in[18];
    const float* eb2 = (const float*)d_in[19];
    float* out = (float*)d_out;

    __half *xh, *w0h, *w1h, *w2h, *yp, *hp, *ap;
    cudaGetSymbolAddress((void**)&xh, g_xh);
    cudaGetSymbolAddress((void**)&w0h, g_w0h);
    cudaGetSymbolAddress((void**)&w1h, g_w1h);
    cudaGetSymbolAddress((void**)&w2h, g_w2h);
    cudaGetSymbolAddress((void**)&yp, g_y);
    cudaGetSymbolAddress((void**)&hp, g_h);
    cudaGetSymbolAddress((void**)&ap, g_act);

    const int WARP_GRID = (NN * 32 + 255) / 256;

    // graph preprocessing (CSR by dst, degrees, dis)
    zero_kernel<<<(NN + 255) / 256, 256>>>();
    count_kernel<<<(EE + 255) / 256, 256>>>(ei, batch);
    scan_kernel<<<1, 1024>>>();
    dis_kernel<<<(NN + 255) / 256, 256>>>();
    fill_kernel<<<(EE + 255) / 256, 256>>>(ei, ea);

    // fp16 conversions (x scaled by dis; weights)
    convert_x_kernel<<<PADN * 32 / 256, 256>>>(x);
    convert_w_kernel<<<80, 256>>>(gw0, gw1, gw2);

    // layer 0: 128 -> 128
    hgemm_kernel<128, 64><<<PADN / 64, 256>>>(xh, w0h, yp);
    gather1_kernel<128><<<WARP_GRID, 256>>>(yp, gb0, hp);
    gather2_ln_kernel<<<WARP_GRID, 256>>>(hp, ew0, eb0, lg0, lb0, ap);

    // layer 1: 128 -> 128
    hgemm_kernel<128, 64><<<PADN / 64, 256>>>(ap, w1h, yp);
    gather1_kernel<128><<<WARP_GRID, 256>>>(yp, gb1, hp);
    gather2_ln_kernel<<<WARP_GRID, 256>>>(hp, ew1, eb1, lg1, lb1, ap);

    // layer 2: 128 -> 64
    hgemm_kernel<64, 128><<<PADN / 128, 256>>>(ap, w2h, yp);
    gather1_kernel<64><<<WARP_GRID, 256>>>(yp, gb2, hp);
    gather2_final_kernel<<<WARP_GRID, 256>>>(hp, ew2, eb2, out);

    // global mean pool into out[NN*64 ..]
    pool_kernel<<<GG, 256>>>(out);
}